// round 14
// baseline (speedup 1.0000x reference)
#include <cuda_runtime.h>
#include <cstdint>

#define Dh 256
#define NMAX 50048
#define EMAX 400128
#define GMAX 512
#define KN 16    // dst-nodes per k_msgs block
#define KC 32    // edges per pipelined chunk

typedef unsigned long long ull;

// ---------------- scratch (device globals; allocation-free) ----------------
__device__ float g_VN[(size_t)NMAX * 16];      // v_norm
__device__ float g_P[(size_t)NMAX * Dh];       // node_s @ WP            (dst part)
__device__ float g_Q[(size_t)NMAX * Dh];       // node_s @ WQ + vn @ W1c (src part)
__device__ float g_R[(size_t)NMAX * Dh];       // segment_sum(relu(hpre), dst)
__device__ int   g_CNT[NMAX];                  // in-degree per node
__device__ int   g_GCNT[GMAX];                 // nodes per graph
__device__ int   g_OFF[NMAX + 1];              // exclusive prefix of CNT
__device__ int   g_POS[NMAX];                  // scatter cursor
__device__ int   g_ESRC[EMAX];                 // src of dst-sorted edges
__device__ float g_ES[(size_t)EMAX * 17];      // edge_s rows in dst-sorted order
// folded weights
__device__ float g_WPfull[64 * Dh];            // rows 0:23 = Ws@Wm1[0:256]
__device__ float g_WQfull[64 * Dh];            // rows 0:23 = Ws@Wm1[256:512], 23:39 = Wm1[512:528]
__device__ float g_WBF[320 * Dh];              // 0:256=Wm2@WnS, 256:279=Ws@WnS, 279:295=Wn[256:272]
__device__ float g_Wed[17 * Dh];               // We[0:17] @ Wm1[528:784]
__device__ float g_bedAll[Dh];                 // bm1 + be@W1d + bs@W1a + bs@W1b
__device__ float g_b0[Dh];                     // bn + bs@WnS
__device__ float g_cB[Dh];                     // bm2@WnS

// ---------------- packed f32x2 helpers ----------------
__device__ __forceinline__ void ffma2(ull &d, ull a, ull b) {
    asm("fma.rn.f32x2 %0, %1, %2, %0;" : "+l"(d) : "l"(a), "l"(b));
}
__device__ __forceinline__ void addf2(ull &d, ull a, ull b) {
    asm("add.rn.f32x2 %0, %1, %2;" : "=l"(d) : "l"(a), "l"(b));
}
__device__ __forceinline__ ull packdup(float a) {
    ull r;
    asm("mov.b64 %0, {%1, %1};" : "=l"(r) : "f"(a));
    return r;
}
__device__ __forceinline__ float2 unpk(ull v) {
    float2 f;
    asm("mov.b64 {%0, %1}, %2;" : "=f"(f.x), "=f"(f.y) : "l"(v));
    return f;
}
__device__ __forceinline__ void atomAdd4(float* p, float4 v) {
    asm volatile("red.global.add.v4.f32 [%0], {%1,%2,%3,%4};"
                 :: "l"(p), "f"(v.x), "f"(v.y), "f"(v.z), "f"(v.w) : "memory");
}
__device__ __forceinline__ ulonglong2 ldg2(const float* p) {
    ulonglong2 v;
    asm("ld.global.nc.v2.u64 {%0, %1}, [%2];" : "=l"(v.x), "=l"(v.y) : "l"(p));
    return v;
}

// ---------------- GEMM core: 8 rows x 8 cols, 16-k chunk; A smem (broadcast), B global/L1 ----------------
__device__ __forceinline__ void mma8_ldg(const float* aRow, int lda, const float* __restrict__ Bg,
                                         int j, ull acc[8][4]) {
#pragma unroll
    for (int kk = 0; kk < 16; kk += 4) {
        float4 a4[8];
#pragma unroll
        for (int r = 0; r < 8; r++)
            a4[r] = *(const float4*)(aRow + r * lda + kk);
#pragma unroll
        for (int u = 0; u < 4; u++) {
            const float* brow = Bg + (kk + u) * Dh + 4 * j;
            ulonglong2 b0 = ldg2(brow);
            ulonglong2 b1 = ldg2(brow + 128);
#pragma unroll
            for (int r = 0; r < 8; r++) {
                float av = (u == 0) ? a4[r].x : (u == 1) ? a4[r].y : (u == 2) ? a4[r].z : a4[r].w;
                ull pa = packdup(av);
                ffma2(acc[r][0], pa, b0.x);
                ffma2(acc[r][1], pa, b0.y);
                ffma2(acc[r][2], pa, b1.x);
                ffma2(acc[r][3], pa, b1.y);
            }
        }
    }
}

// ---------------- k_zero ----------------
__global__ void k_zero(float* out, int outN, int N, int G) {
    int stride = gridDim.x * blockDim.x;
    int idx0 = blockIdx.x * blockDim.x + threadIdx.x;
    for (int i = idx0; i < outN; i += stride) out[i] = 0.f;
    for (int i = idx0; i < N; i += stride) g_CNT[i] = 0;
    for (int i = idx0; i < G; i += stride) g_GCNT[i] = 0;
}

// ---------------- k_cnt ----------------
__global__ void k_cnt(const int* __restrict__ ei, const int* __restrict__ batch, int E, int N) {
    int idx = blockIdx.x * blockDim.x + threadIdx.x;
    if (idx < E) atomicAdd(&g_CNT[ei[(size_t)E + idx]], 1);
    if (idx < N) atomicAdd(&g_GCNT[batch[idx]], 1);
}

// ---------------- k_scan ----------------
__global__ void __launch_bounds__(1024) k_scan(int N) {
    __shared__ int part[1024];
    int t = threadIdx.x;
    int chunk = (N + 1023) >> 10;
    int beg = t * chunk, end = beg + chunk;
    if (end > N) end = N;
    int s = 0;
    for (int i = beg; i < end; i++) s += g_CNT[i];
    part[t] = s;
    __syncthreads();
    for (int off = 1; off < 1024; off <<= 1) {
        int v = (t >= off) ? part[t - off] : 0;
        __syncthreads();
        part[t] += v;
        __syncthreads();
    }
    int base = (t == 0) ? 0 : part[t - 1];
    for (int i = beg; i < end; i++) {
        g_OFF[i] = base;
        g_POS[i] = base;
        base += g_CNT[i];
    }
    if (t == 1023) g_OFF[N] = part[1023];
}

// ---------------- k_scatter ----------------
__global__ void k_scatter(const int* __restrict__ ei, const float* __restrict__ edge_s, int E) {
    int e = blockIdx.x * blockDim.x + threadIdx.x;
    if (e < E) {
        int d = ei[(size_t)E + e];
        int pos = atomicAdd(&g_POS[d], 1);
        g_ESRC[pos] = ei[e];
        const float* src = edge_s + (size_t)e * 17;
        float* dst = g_ES + (size_t)pos * 17;
#pragma unroll
        for (int j = 0; j < 17; j++) dst[j] = src[j];
    }
}

// ---------------- k_prep ----------------
__global__ void k_prep(const float* __restrict__ Ws, const float* __restrict__ bs,
                       const float* __restrict__ We, const float* __restrict__ be,
                       const float* __restrict__ Wm1, const float* __restrict__ bm1,
                       const float* __restrict__ Wm2, const float* __restrict__ bm2,
                       const float* __restrict__ Wn, const float* __restrict__ bn) {
    __shared__ float a[256];
    __shared__ float a2[256];
    int t = threadIdx.x, b = blockIdx.x;
    const float* W1a = Wm1;
    const float* W1b = Wm1 + (size_t)256 * 256;
    const float* W1d = Wm1 + (size_t)528 * 256;
    const float* WnS = Wn;

    if (b < 64) {
        int r = b;
        if (r < 23) {
            a[t] = Ws[(size_t)r * 256 + t];
            __syncthreads();
            float acc = 0.f;
            for (int k = 0; k < 256; k++) acc = fmaf(a[k], W1a[(size_t)k * 256 + t], acc);
            g_WPfull[r * 256 + t] = acc;
        } else g_WPfull[r * 256 + t] = 0.f;
    } else if (b < 128) {
        int r = b - 64;
        if (r < 23) {
            a[t] = Ws[(size_t)r * 256 + t];
            __syncthreads();
            float acc = 0.f;
            for (int k = 0; k < 256; k++) acc = fmaf(a[k], W1b[(size_t)k * 256 + t], acc);
            g_WQfull[r * 256 + t] = acc;
        } else if (r < 39) {
            g_WQfull[r * 256 + t] = Wm1[(size_t)(512 + (r - 23)) * 256 + t];
        } else g_WQfull[r * 256 + t] = 0.f;
    } else if (b < 448) {
        int r = b - 128;
        if (r < 256) {
            a[t] = Wm2[(size_t)r * 256 + t];
            __syncthreads();
            float acc = 0.f;
            for (int k = 0; k < 256; k++) acc = fmaf(a[k], WnS[(size_t)k * 256 + t], acc);
            g_WBF[r * 256 + t] = acc;
        } else if (r < 279) {
            a[t] = Ws[(size_t)(r - 256) * 256 + t];
            __syncthreads();
            float acc = 0.f;
            for (int k = 0; k < 256; k++) acc = fmaf(a[k], WnS[(size_t)k * 256 + t], acc);
            g_WBF[r * 256 + t] = acc;
        } else if (r < 295) {
            g_WBF[r * 256 + t] = Wn[(size_t)(256 + (r - 279)) * 256 + t];
        } else g_WBF[r * 256 + t] = 0.f;
    } else if (b < 465) {
        int r = b - 448;
        a[t] = We[(size_t)r * 256 + t];
        __syncthreads();
        float acc = 0.f;
        for (int k = 0; k < 256; k++) acc = fmaf(a[k], W1d[(size_t)k * 256 + t], acc);
        g_Wed[r * 256 + t] = acc;
    } else if (b == 465) {
        a[t] = bs[t]; a2[t] = be[t];
        __syncthreads();
        float acc = bm1[t];
        for (int k = 0; k < 256; k++) {
            acc = fmaf(a[k], W1a[(size_t)k * 256 + t], acc);
            acc = fmaf(a[k], W1b[(size_t)k * 256 + t], acc);
            acc = fmaf(a2[k], W1d[(size_t)k * 256 + t], acc);
        }
        g_bedAll[t] = acc;
    } else if (b == 466) {
        a[t] = bs[t];
        __syncthreads();
        float acc = bn[t];
        for (int k = 0; k < 256; k++) acc = fmaf(a[k], WnS[(size_t)k * 256 + t], acc);
        g_b0[t] = acc;
    } else {
        a[t] = bm2[t];
        __syncthreads();
        float acc = 0.f;
        for (int k = 0; k < 256; k++) acc = fmaf(a[k], WnS[(size_t)k * 256 + t], acc);
        g_cB[t] = acc;
    }
}

// ---------------- k_vn ----------------
__global__ void k_vn(const float* __restrict__ node_v, const float* __restrict__ Wv,
                     const float* __restrict__ bv, int N) {
    __shared__ float sWv[64], sBv[16];
    int t = threadIdx.x;
    if (t < 64) sWv[t] = Wv[t];
    else if (t < 80) sBv[t - 64] = bv[t - 64];
    __syncthreads();
    int idx = blockIdx.x * blockDim.x + t;
    if (idx < N * 16) {
        int n = idx >> 4, o = idx & 15;
        float ss = 0.f;
#pragma unroll
        for (int c = 0; c < 3; c++) {
            float v = sBv[o];
#pragma unroll
            for (int k = 0; k < 4; k++) v = fmaf(node_v[(size_t)n * 12 + k * 3 + c], sWv[k * 16 + o], v);
            ss = fmaf(v, v, ss);
        }
        g_VN[idx] = sqrtf(ss);
    }
}

// ---------------- k_pq: BM=64, 8x8 tile, barrier-free mainloop, B via LDG/L1 ----------------
__global__ void __launch_bounds__(256, 2) k_pq(const float* __restrict__ node_s, int N) {
    extern __shared__ float sm[];
    float* sA = sm;                // 64 x KCq (max 64x64 = 16KB)
    int t = threadIdx.x;
    int n0 = blockIdx.x * 64;
    int isQ = blockIdx.y;
    const float* B = isQ ? g_WQfull : g_WPfull;
    float* OUT = isQ ? g_Q : g_P;
    int KCq = isQ ? 64 : 32;

    for (int idx = t; idx < 64 * KCq; idx += 256) {
        int m = idx / KCq, c = idx - m * KCq;
        int n = n0 + m;
        float v = 0.f;
        if (n < N) {
            if (c < 23) v = node_s[(size_t)n * 23 + c];
            else if (c < 39 && isQ) v = g_VN[(size_t)n * 16 + (c - 23)];
        }
        sA[idx] = v;
    }
    __syncthreads();

    int i = t >> 5, j = t & 31;
    ull acc[8][4];
#pragma unroll
    for (int r = 0; r < 8; r++)
#pragma unroll
        for (int c = 0; c < 4; c++) acc[r][c] = 0ull;

    for (int k0 = 0; k0 < KCq; k0 += 16)
        mma8_ldg(sA + (i * 8) * KCq + k0, KCq, B + (size_t)k0 * Dh, j, acc);

#pragma unroll
    for (int r = 0; r < 8; r++) {
        int n = n0 + i * 8 + r;
        if (n < N) {
            float2 a0 = unpk(acc[r][0]), a1 = unpk(acc[r][1]);
            float2 a2 = unpk(acc[r][2]), a3 = unpk(acc[r][3]);
            *(float4*)(OUT + (size_t)n * Dh + 4 * j)       = make_float4(a0.x, a0.y, a1.x, a1.y);
            *(float4*)(OUT + (size_t)n * Dh + 128 + 4 * j) = make_float4(a2.x, a2.y, a3.x, a3.y);
        }
    }
}

// ---------------- k_msgs: pipelined sequential-stream message accumulation (R8 best) ----------------
__global__ void __launch_bounds__(128) k_msgs(int N) {
    __shared__ float sP[KN * 256];
    __shared__ ull   sES[2][KC * 17];
    __shared__ int   sSrc[2][KC];
    __shared__ int   sNd[2][KC];
    __shared__ int   sOff[KN + 1];

    int t = threadIdx.x;
    int n0 = blockIdx.x * KN;
    int nCnt = N - n0; if (nCnt > KN) nCnt = KN;
    if (t <= nCnt) sOff[t] = g_OFF[n0 + t];
    __syncthreads();
    int eBeg = sOff[0], eEnd = sOff[nCnt];
    if (eBeg == eEnd) return;

    for (int idx = t; idx < nCnt * 64; idx += 128) {
        int m = idx >> 6, c4 = idx & 63;
        *(float4*)(sP + m * 256 + c4 * 4) = *(const float4*)(g_P + (size_t)(n0 + m) * Dh + c4 * 4);
    }

    ull wed2[17];
#pragma unroll
    for (int j = 0; j < 17; j++) wed2[j] = *(const ull*)(g_Wed + j * 256 + 2 * t);
    ull bed2 = *(const ull*)(g_bedAll + 2 * t);

    {
        int len = eEnd - eBeg; if (len > KC) len = KC;
#pragma unroll
        for (int u = 0; u < 5; u++) {
            int idx = t + u * 128;
            if (idx < KC * 17) {
                float v = (idx < len * 17) ? g_ES[(size_t)eBeg * 17 + idx] : 0.f;
                sES[0][idx] = packdup(v);
            }
        }
        if (t < KC) {
            int pos = eBeg + t;
            int src = 0, nd = nCnt - 1;
            if (pos < eEnd) {
                src = g_ESRC[pos];
                nd = 0;
                for (int i = 1; i < nCnt; i++) nd += (pos >= sOff[i]);
            }
            sSrc[0][t] = src;
            sNd[0][t] = nd;
        }
    }
    __syncthreads();

    int cur = -1;
    float2 acc = make_float2(0.f, 0.f);
    ull pcur = 0ull;
    int buf = 0;

    for (int cb = eBeg; cb < eEnd; cb += KC, buf ^= 1) {
        int len = eEnd - cb; if (len > KC) len = KC;

        float nv[5];
        int nsrc = 0, nnd = nCnt - 1;
        int cb2 = cb + KC;
        bool more = (cb2 < eEnd);
        int len2 = eEnd - cb2; if (len2 > KC) len2 = KC;
#pragma unroll
        for (int u = 0; u < 5; u++) {
            int idx = t + u * 128;
            nv[u] = 0.f;
            if (more && idx < KC * 17 && idx < len2 * 17)
                nv[u] = g_ES[(size_t)cb2 * 17 + idx];
        }
        if (more && t < KC) {
            int pos = cb2 + t;
            if (pos < eEnd) {
                nsrc = g_ESRC[pos];
                nnd = 0;
                for (int i = 1; i < nCnt; i++) nnd += (pos >= sOff[i]);
            }
        }

        for (int b = 0; b < len; b += 4) {
            ull q[4];
#pragma unroll
            for (int k = 0; k < 4; k++) {
                int src = sSrc[buf][b + k];
                q[k] = *(const ull*)(g_Q + (size_t)src * Dh + 2 * t);
            }
            ull r[4] = {bed2, bed2, bed2, bed2};
#pragma unroll
            for (int j = 0; j < 17; j++) {
                ull w = wed2[j];
#pragma unroll
                for (int k = 0; k < 4; k++)
                    ffma2(r[k], sES[buf][(b + k) * 17 + j], w);
            }
#pragma unroll
            for (int k = 0; k < 4; k++) {
                if (b + k >= len) break;
                int nd = sNd[buf][b + k];
                if (nd != cur) {
                    if (cur >= 0)
                        *(float2*)(g_R + (size_t)(n0 + cur) * Dh + 2 * t) = acc;
                    cur = nd;
                    pcur = *(const ull*)(sP + nd * 256 + 2 * t);
                    acc = make_float2(0.f, 0.f);
                }
                ull s1;
                addf2(s1, pcur, q[k]);
                addf2(s1, s1, r[k]);
                float2 f = unpk(s1);
                acc.x += fmaxf(f.x, 0.f);
                acc.y += fmaxf(f.y, 0.f);
            }
        }

        if (more) {
#pragma unroll
            for (int u = 0; u < 5; u++) {
                int idx = t + u * 128;
                if (idx < KC * 17) sES[buf ^ 1][idx] = packdup(nv[u]);
            }
            if (t < KC) { sSrc[buf ^ 1][t] = nsrc; sNd[buf ^ 1][t] = nnd; }
        }
        __syncthreads();
    }
    if (cur >= 0)
        *(float2*)(g_R + (size_t)(n0 + cur) * Dh + 2 * t) = acc;
}

// ---------------- k_final: BM=64, 8x8 tile, barrier-free mainloop, B via LDG/L1 ----------------
__global__ void __launch_bounds__(256, 2) k_final(const float* __restrict__ node_s,
                                                  const float* __restrict__ gamma, const float* __restrict__ beta,
                                                  const int* __restrict__ batch, float* __restrict__ out, int N) {
    extern __shared__ float sm[];
    float* sA = sm;                 // 64*320
    float* sInv = sA + 64 * 320;    // 64
    float* sChi = sInv + 64;        // 64
    int t = threadIdx.x;
    int n0 = blockIdx.x * 64;

    if (t < 64) {
        int n = n0 + t;
        int c = (n < N) ? g_CNT[n] : 0;
        sInv[t] = (c > 0) ? (1.f / (float)c) : 0.f;
        sChi[t] = (c > 0) ? 1.f : 0.f;
    }
    __syncthreads();
    // Rbar (cols 0:256) as float4: 64x64 quads
    for (int q = 0; q < 16; q++) {
        int idx = t + q * 256;
        int m = idx >> 6, c4 = idx & 63;
        int n = n0 + m;
        float4 v = make_float4(0.f, 0.f, 0.f, 0.f);
        if (n < N) {
            float inv = sInv[m];
            if (inv != 0.f) {
                float4 r = *(const float4*)(g_R + (size_t)n * Dh + c4 * 4);
                v = make_float4(r.x * inv, r.y * inv, r.z * inv, r.w * inv);
            }
        }
        *(float4*)(sA + m * 320 + c4 * 4) = v;
    }
    // node_s (256:279), vn (279:295), pad (295:320): 64x64 scalars
    for (int q = 0; q < 16; q++) {
        int idx = t + q * 256;
        int m = idx >> 6, c = idx & 63;
        int n = n0 + m;
        float v = 0.f;
        if (n < N) {
            if (c < 23)      v = node_s[(size_t)n * 23 + c];
            else if (c < 39) v = g_VN[(size_t)n * 16 + (c - 23)];
        }
        sA[m * 320 + 256 + c] = v;
    }
    __syncthreads();

    int i = t >> 5, j = t & 31;
    ull acc[8][4];
#pragma unroll
    for (int r = 0; r < 8; r++)
#pragma unroll
        for (int c = 0; c < 4; c++) acc[r][c] = 0ull;

    for (int k0 = 0; k0 < 304; k0 += 16)
        mma8_ldg(sA + (i * 8) * 320 + k0, 320, g_WBF + (size_t)k0 * Dh, j, acc);

    float4 b00 = *(const float4*)(g_b0 + 4 * j);
    float4 b01 = *(const float4*)(g_b0 + 128 + 4 * j);
    float4 cb0 = *(const float4*)(g_cB + 4 * j);
    float4 cb1 = *(const float4*)(g_cB + 128 + 4 * j);
    float4 g0  = *(const float4*)(gamma + 4 * j);
    float4 g1  = *(const float4*)(gamma + 128 + 4 * j);
    float4 be0 = *(const float4*)(beta + 4 * j);
    float4 be1 = *(const float4*)(beta + 128 + 4 * j);
#pragma unroll
    for (int r = 0; r < 8; r++) {
        int n = n0 + i * 8 + r;
        float chi = sChi[i * 8 + r];
        float2 a0 = unpk(acc[r][0]), a1 = unpk(acc[r][1]);
        float2 a2 = unpk(acc[r][2]), a3 = unpk(acc[r][3]);
        float f[8];
        f[0] = a0.x + b00.x + chi * cb0.x; f[1] = a0.y + b00.y + chi * cb0.y;
        f[2] = a1.x + b00.z + chi * cb0.z; f[3] = a1.y + b00.w + chi * cb0.w;
        f[4] = a2.x + b01.x + chi * cb1.x; f[5] = a2.y + b01.y + chi * cb1.y;
        f[6] = a3.x + b01.z + chi * cb1.z; f[7] = a3.y + b01.w + chi * cb1.w;
        float s = 0.f, sq = 0.f;
#pragma unroll
        for (int c = 0; c < 8; c++) { s += f[c]; sq = fmaf(f[c], f[c], sq); }
#pragma unroll
        for (int off = 16; off > 0; off >>= 1) {
            s  += __shfl_xor_sync(0xFFFFFFFFu, s, off);
            sq += __shfl_xor_sync(0xFFFFFFFFu, sq, off);
        }
        float mu = s * (1.f / 256.f);
        float var = sq * (1.f / 256.f) - mu * mu;
        float rs = rsqrtf(var + 1e-5f);
        float y[8];
        y[0] = fmaxf((f[0] - mu) * rs * g0.x + be0.x, 0.f);
        y[1] = fmaxf((f[1] - mu) * rs * g0.y + be0.y, 0.f);
        y[2] = fmaxf((f[2] - mu) * rs * g0.z + be0.z, 0.f);
        y[3] = fmaxf((f[3] - mu) * rs * g0.w + be0.w, 0.f);
        y[4] = fmaxf((f[4] - mu) * rs * g1.x + be1.x, 0.f);
        y[5] = fmaxf((f[5] - mu) * rs * g1.y + be1.y, 0.f);
        y[6] = fmaxf((f[6] - mu) * rs * g1.z + be1.z, 0.f);
        y[7] = fmaxf((f[7] - mu) * rs * g1.w + be1.w, 0.f);
        if (n < N) {
            int b = batch[n];
            atomAdd4(out + (size_t)b * Dh + 4 * j,       make_float4(y[0], y[1], y[2], y[3]));
            atomAdd4(out + (size_t)b * Dh + 128 + 4 * j, make_float4(y[4], y[5], y[6], y[7]));
        }
    }
}

// ---------------- k_div ----------------
__global__ void k_div(float* out, int G) {
    int idx = blockIdx.x * blockDim.x + threadIdx.x;
    if (idx < G * Dh) {
        float c = (float)g_GCNT[idx >> 8];
        out[idx] *= 1.f / fmaxf(c, 1.f);
    }
}

// ---------------- launch ----------------
extern "C" void kernel_launch(void* const* d_in, const int* in_sizes, int n_in,
                              void* d_out, int out_size) {
    const float* node_s     = (const float*)d_in[0];
    const float* node_v     = (const float*)d_in[1];
    const float* edge_s     = (const float*)d_in[2];
    const int*   edge_index = (const int*)d_in[3];
    const int*   batch      = (const int*)d_in[4];
    const float* Ws  = (const float*)d_in[5];
    const float* bs  = (const float*)d_in[6];
    const float* Wv  = (const float*)d_in[7];
    const float* bv  = (const float*)d_in[8];
    const float* We  = (const float*)d_in[9];
    const float* be  = (const float*)d_in[10];
    const float* Wm1 = (const float*)d_in[11];
    const float* bm1 = (const float*)d_in[12];
    const float* Wm2 = (const float*)d_in[13];
    const float* bm2 = (const float*)d_in[14];
    const float* Wn  = (const float*)d_in[15];
    const float* bn  = (const float*)d_in[16];
    const float* gamma = (const float*)d_in[17];
    const float* beta  = (const float*)d_in[18];

    int N = in_sizes[0] / 23;
    int E = in_sizes[2] / 17;
    int G = out_size / Dh;
    float* out = (float*)d_out;

    const int SM_PQ    = 64 * 64 * 4;                       // 16384
    const int SM_FINAL = (64 * 320 + 128) * 4;              // 82432
    cudaFuncSetAttribute((const void*)k_pq,    cudaFuncAttributeMaxDynamicSharedMemorySize, SM_PQ);
    cudaFuncSetAttribute((const void*)k_final, cudaFuncAttributeMaxDynamicSharedMemorySize, SM_FINAL);

    int mEN = (E > N) ? E : N;

    // 4th launch (= ncu sample slot) is k_pq
    k_zero<<<456, 256>>>(out, out_size, N, G);
    k_prep<<<468, 256>>>(Ws, bs, We, be, Wm1, bm1, Wm2, bm2, Wn, bn);
    k_vn<<<(N * 16 + 255) / 256, 256>>>(node_v, Wv, bv, N);
    dim3 gpq((N + 63) / 64, 2);
    k_pq<<<gpq, 256, SM_PQ>>>(node_s, N);
    k_cnt<<<(mEN + 255) / 256, 256>>>(edge_index, batch, E, N);
    k_scan<<<1, 1024>>>(N);
    k_scatter<<<(E + 255) / 256, 256>>>(edge_index, edge_s, E);
    k_msgs<<<(N + KN - 1) / KN, 128>>>(N);
    k_final<<<(N + 63) / 64, 256, SM_FINAL>>>(node_s, gamma, beta, batch, out, N);
    k_div<<<(G * Dh + 255) / 256, 256>>>(out, G);
}

// round 15
// speedup vs baseline: 1.1927x; 1.1927x over previous
#include <cuda_runtime.h>
#include <cstdint>

#define Dh 256
#define NMAX 50048
#define EMAX 400128
#define GMAX 512
#define KN 16    // dst-nodes per k_msgs block
#define KC 32    // edges per pipelined chunk

typedef unsigned long long ull;

// ---------------- scratch (device globals; allocation-free) ----------------
__device__ float g_VN[(size_t)NMAX * 16];      // v_norm
__device__ float g_P[(size_t)NMAX * Dh];       // node_s @ WP            (dst part)
__device__ float g_Q[(size_t)NMAX * Dh];       // node_s @ WQ + vn @ W1c (src part)
__device__ float g_R[(size_t)NMAX * Dh];       // segment_sum(relu(hpre), dst)
__device__ int   g_CNT[NMAX];                  // in-degree per node
__device__ int   g_GCNT[GMAX];                 // nodes per graph
__device__ int   g_OFF[NMAX + 1];              // exclusive prefix of CNT
__device__ int   g_POS[NMAX];                  // scatter cursor
__device__ int   g_ESRC[EMAX];                 // src of dst-sorted edges
__device__ float g_ES[(size_t)EMAX * 17];      // edge_s rows in dst-sorted order
// folded weights
__device__ float g_WPfull[64 * Dh];            // rows 0:23 = Ws@Wm1[0:256]
__device__ float g_WQfull[64 * Dh];            // rows 0:23 = Ws@Wm1[256:512], 23:39 = Wm1[512:528]
__device__ float g_WBF[320 * Dh];              // 0:256=Wm2@WnS, 256:279=Ws@WnS, 279:295=Wn[256:272]
__device__ float g_Wed[17 * Dh];               // We[0:17] @ Wm1[528:784]
__device__ float g_bedAll[Dh];                 // bm1 + be@W1d + bs@W1a + bs@W1b
__device__ float g_b0[Dh];                     // bn + bs@WnS
__device__ float g_cB[Dh];                     // bm2@WnS

// ---------------- packed f32x2 helpers ----------------
__device__ __forceinline__ void ffma2(ull &d, ull a, ull b) {
    asm("fma.rn.f32x2 %0, %1, %2, %0;" : "+l"(d) : "l"(a), "l"(b));
}
__device__ __forceinline__ void addf2(ull &d, ull a, ull b) {
    asm("add.rn.f32x2 %0, %1, %2;" : "=l"(d) : "l"(a), "l"(b));
}
__device__ __forceinline__ ull packdup(float a) {
    ull r;
    asm("mov.b64 %0, {%1, %1};" : "=l"(r) : "f"(a));
    return r;
}
__device__ __forceinline__ float2 unpk(ull v) {
    float2 f;
    asm("mov.b64 {%0, %1}, %2;" : "=f"(f.x), "=f"(f.y) : "l"(v));
    return f;
}
__device__ __forceinline__ void atomAdd4(float* p, float4 v) {
    asm volatile("red.global.add.v4.f32 [%0], {%1,%2,%3,%4};"
                 :: "l"(p), "f"(v.x), "f"(v.y), "f"(v.z), "f"(v.w) : "memory");
}
__device__ __forceinline__ uint32_t smem_u32(const void* p) {
    uint32_t a;
    asm("{ .reg .u64 t; cvta.to.shared.u64 t, %1; cvt.u32.u64 %0, t; }" : "=r"(a) : "l"(p));
    return a;
}
__device__ __forceinline__ void cp_async16(uint32_t saddr, const void* gptr) {
    asm volatile("cp.async.ca.shared.global [%0], [%1], 16;" :: "r"(saddr), "l"(gptr));
}
#define CP_COMMIT()  asm volatile("cp.async.commit_group;" ::: "memory")
#define CP_WAIT(n)   asm volatile("cp.async.wait_group %0;" :: "n"(n) : "memory")

// ---------------- GEMM building blocks (BM=64, BN=256, 256 threads) ----------------
__device__ __forceinline__ void stage_B16_async(uint32_t sBaddr, const float* __restrict__ B,
                                                int k0, int t) {
#pragma unroll
    for (int q = 0; q < 4; q++) {
        int idx = t + q * 256;
        int kk = idx >> 6, c4 = idx & 63;
        cp_async16(sBaddr + (uint32_t)(kk * Dh + c4 * 4) * 4,
                   B + (size_t)(k0 + kk) * Dh + c4 * 4);
    }
}

__device__ __forceinline__ void mma_chunk16(const float* aRow, int lda, const float* sB,
                                            int j, ull acc[8][4]) {
#pragma unroll
    for (int kk = 0; kk < 16; kk += 4) {
        float4 a4[8];
#pragma unroll
        for (int r = 0; r < 8; r++)
            a4[r] = *(const float4*)(aRow + r * lda + kk);
#pragma unroll
        for (int u = 0; u < 4; u++) {
            const float* brow = sB + (kk + u) * Dh + 4 * j;
            ulonglong2 b0 = *(const ulonglong2*)(brow);
            ulonglong2 b1 = *(const ulonglong2*)(brow + 128);
#pragma unroll
            for (int r = 0; r < 8; r++) {
                float av = (u == 0) ? a4[r].x : (u == 1) ? a4[r].y : (u == 2) ? a4[r].z : a4[r].w;
                ull pa = packdup(av);
                ffma2(acc[r][0], pa, b0.x);
                ffma2(acc[r][1], pa, b0.y);
                ffma2(acc[r][2], pa, b1.x);
                ffma2(acc[r][3], pa, b1.y);
            }
        }
    }
}

// ---------------- k_zero ----------------
__global__ void k_zero(float* out, int outN, int N, int G) {
    int stride = gridDim.x * blockDim.x;
    int idx0 = blockIdx.x * blockDim.x + threadIdx.x;
    for (int i = idx0; i < outN; i += stride) out[i] = 0.f;
    for (int i = idx0; i < N; i += stride) g_CNT[i] = 0;
    for (int i = idx0; i < G; i += stride) g_GCNT[i] = 0;
}

// ---------------- k_cnt ----------------
__global__ void k_cnt(const int* __restrict__ ei, const int* __restrict__ batch, int E, int N) {
    int idx = blockIdx.x * blockDim.x + threadIdx.x;
    if (idx < E) atomicAdd(&g_CNT[ei[(size_t)E + idx]], 1);
    if (idx < N) atomicAdd(&g_GCNT[batch[idx]], 1);
}

// ---------------- k_scan ----------------
__global__ void __launch_bounds__(1024) k_scan(int N) {
    __shared__ int part[1024];
    int t = threadIdx.x;
    int chunk = (N + 1023) >> 10;
    int beg = t * chunk, end = beg + chunk;
    if (end > N) end = N;
    int s = 0;
    for (int i = beg; i < end; i++) s += g_CNT[i];
    part[t] = s;
    __syncthreads();
    for (int off = 1; off < 1024; off <<= 1) {
        int v = (t >= off) ? part[t - off] : 0;
        __syncthreads();
        part[t] += v;
        __syncthreads();
    }
    int base = (t == 0) ? 0 : part[t - 1];
    for (int i = beg; i < end; i++) {
        g_OFF[i] = base;
        g_POS[i] = base;
        base += g_CNT[i];
    }
    if (t == 1023) g_OFF[N] = part[1023];
}

// ---------------- k_scatter ----------------
__global__ void k_scatter(const int* __restrict__ ei, const float* __restrict__ edge_s, int E) {
    int e = blockIdx.x * blockDim.x + threadIdx.x;
    if (e < E) {
        int d = ei[(size_t)E + e];
        int pos = atomicAdd(&g_POS[d], 1);
        g_ESRC[pos] = ei[e];
        const float* src = edge_s + (size_t)e * 17;
        float* dst = g_ES + (size_t)pos * 17;
#pragma unroll
        for (int j = 0; j < 17; j++) dst[j] = src[j];
    }
}

// ---------------- k_prep ----------------
__global__ void k_prep(const float* __restrict__ Ws, const float* __restrict__ bs,
                       const float* __restrict__ We, const float* __restrict__ be,
                       const float* __restrict__ Wm1, const float* __restrict__ bm1,
                       const float* __restrict__ Wm2, const float* __restrict__ bm2,
                       const float* __restrict__ Wn, const float* __restrict__ bn) {
    __shared__ float a[256];
    __shared__ float a2[256];
    int t = threadIdx.x, b = blockIdx.x;
    const float* W1a = Wm1;
    const float* W1b = Wm1 + (size_t)256 * 256;
    const float* W1d = Wm1 + (size_t)528 * 256;
    const float* WnS = Wn;

    if (b < 64) {
        int r = b;
        if (r < 23) {
            a[t] = Ws[(size_t)r * 256 + t];
            __syncthreads();
            float acc = 0.f;
            for (int k = 0; k < 256; k++) acc = fmaf(a[k], W1a[(size_t)k * 256 + t], acc);
            g_WPfull[r * 256 + t] = acc;
        } else g_WPfull[r * 256 + t] = 0.f;
    } else if (b < 128) {
        int r = b - 64;
        if (r < 23) {
            a[t] = Ws[(size_t)r * 256 + t];
            __syncthreads();
            float acc = 0.f;
            for (int k = 0; k < 256; k++) acc = fmaf(a[k], W1b[(size_t)k * 256 + t], acc);
            g_WQfull[r * 256 + t] = acc;
        } else if (r < 39) {
            g_WQfull[r * 256 + t] = Wm1[(size_t)(512 + (r - 23)) * 256 + t];
        } else g_WQfull[r * 256 + t] = 0.f;
    } else if (b < 448) {
        int r = b - 128;
        if (r < 256) {
            a[t] = Wm2[(size_t)r * 256 + t];
            __syncthreads();
            float acc = 0.f;
            for (int k = 0; k < 256; k++) acc = fmaf(a[k], WnS[(size_t)k * 256 + t], acc);
            g_WBF[r * 256 + t] = acc;
        } else if (r < 279) {
            a[t] = Ws[(size_t)(r - 256) * 256 + t];
            __syncthreads();
            float acc = 0.f;
            for (int k = 0; k < 256; k++) acc = fmaf(a[k], WnS[(size_t)k * 256 + t], acc);
            g_WBF[r * 256 + t] = acc;
        } else if (r < 295) {
            g_WBF[r * 256 + t] = Wn[(size_t)(256 + (r - 279)) * 256 + t];
        } else g_WBF[r * 256 + t] = 0.f;
    } else if (b < 465) {
        int r = b - 448;
        a[t] = We[(size_t)r * 256 + t];
        __syncthreads();
        float acc = 0.f;
        for (int k = 0; k < 256; k++) acc = fmaf(a[k], W1d[(size_t)k * 256 + t], acc);
        g_Wed[r * 256 + t] = acc;
    } else if (b == 465) {
        a[t] = bs[t]; a2[t] = be[t];
        __syncthreads();
        float acc = bm1[t];
        for (int k = 0; k < 256; k++) {
            acc = fmaf(a[k], W1a[(size_t)k * 256 + t], acc);
            acc = fmaf(a[k], W1b[(size_t)k * 256 + t], acc);
            acc = fmaf(a2[k], W1d[(size_t)k * 256 + t], acc);
        }
        g_bedAll[t] = acc;
    } else if (b == 466) {
        a[t] = bs[t];
        __syncthreads();
        float acc = bn[t];
        for (int k = 0; k < 256; k++) acc = fmaf(a[k], WnS[(size_t)k * 256 + t], acc);
        g_b0[t] = acc;
    } else {
        a[t] = bm2[t];
        __syncthreads();
        float acc = 0.f;
        for (int k = 0; k < 256; k++) acc = fmaf(a[k], WnS[(size_t)k * 256 + t], acc);
        g_cB[t] = acc;
    }
}

// ---------------- k_vn ----------------
__global__ void k_vn(const float* __restrict__ node_v, const float* __restrict__ Wv,
                     const float* __restrict__ bv, int N) {
    __shared__ float sWv[64], sBv[16];
    int t = threadIdx.x;
    if (t < 64) sWv[t] = Wv[t];
    else if (t < 80) sBv[t - 64] = bv[t - 64];
    __syncthreads();
    int idx = blockIdx.x * blockDim.x + t;
    if (idx < N * 16) {
        int n = idx >> 4, o = idx & 15;
        float ss = 0.f;
#pragma unroll
        for (int c = 0; c < 3; c++) {
            float v = sBv[o];
#pragma unroll
            for (int k = 0; k < 4; k++) v = fmaf(node_v[(size_t)n * 12 + k * 3 + c], sWv[k * 16 + o], v);
            ss = fmaf(v, v, ss);
        }
        g_VN[idx] = sqrtf(ss);
    }
}

// ---------------- k_pq: R11 champion (BM=64, 8x8, cp.async 2-buffer) ----------------
__global__ void __launch_bounds__(256, 2) k_pq(const float* __restrict__ node_s, int N) {
    extern __shared__ float sm[];
    float* sA = sm;               // 64*64
    float* sB = sm + 64 * 64;     // 2 x 16*256
    int t = threadIdx.x;
    int n0 = blockIdx.x * 64;
    int isQ = blockIdx.y;
    const float* B = isQ ? g_WQfull : g_WPfull;
    float* OUT = isQ ? g_Q : g_P;
    int KCq = isQ ? 64 : 32;
    int nCh = KCq >> 4;
    uint32_t sBa = smem_u32(sB);

    stage_B16_async(sBa, B, 0, t);
    CP_COMMIT();

    if (isQ) {
        for (int q = 0; q < 16; q++) {
            int idx = t + q * 256;
            int m = idx >> 6, c = idx & 63;
            int n = n0 + m;
            float v = 0.f;
            if (n < N) {
                if (c < 23) v = node_s[(size_t)n * 23 + c];
                else if (c < 39) v = g_VN[(size_t)n * 16 + (c - 23)];
            }
            sA[m * 64 + c] = v;
        }
    } else {
        for (int q = 0; q < 8; q++) {
            int idx = t + q * 256;
            int m = idx >> 5, c = idx & 31;
            int n = n0 + m;
            float v = 0.f;
            if (n < N && c < 23) v = node_s[(size_t)n * 23 + c];
            sA[m * 32 + c] = v;
        }
    }

    int i = t >> 5, j = t & 31;
    ull acc[8][4];
#pragma unroll
    for (int r = 0; r < 8; r++)
#pragma unroll
        for (int c = 0; c < 4; c++) acc[r][c] = 0ull;

    for (int ch = 0; ch < nCh; ch++) {
        if (ch + 1 < nCh) {
            stage_B16_async(sBa + (uint32_t)(((ch + 1) & 1) * 16 * Dh) * 4, B, (ch + 1) * 16, t);
            CP_COMMIT();
            CP_WAIT(1);
        } else {
            CP_WAIT(0);
        }
        __syncthreads();
        mma_chunk16(sA + i * 8 * KCq + ch * 16, KCq, sB + (ch & 1) * 16 * Dh, j, acc);
        __syncthreads();
    }
#pragma unroll
    for (int r = 0; r < 8; r++) {
        int n = n0 + i * 8 + r;
        if (n < N) {
            float2 a0 = unpk(acc[r][0]), a1 = unpk(acc[r][1]);
            float2 a2 = unpk(acc[r][2]), a3 = unpk(acc[r][3]);
            *(float4*)(OUT + (size_t)n * Dh + 4 * j)       = make_float4(a0.x, a0.y, a1.x, a1.y);
            *(float4*)(OUT + (size_t)n * Dh + 128 + 4 * j) = make_float4(a2.x, a2.y, a3.x, a3.y);
        }
    }
}

// ---------------- k_msgs: pipelined stream w/ LDS.128 edge features (stride-18 sES) ----------------
__global__ void __launch_bounds__(128) k_msgs(int N) {
    __shared__ float sP[KN * 256];
    __shared__ __align__(16) ull sES[2][KC * 18];   // stride 18: rows 16B-aligned
    __shared__ int   sSrc[2][KC];
    __shared__ int   sNd[2][KC];
    __shared__ int   sOff[KN + 1];

    int t = threadIdx.x;
    int n0 = blockIdx.x * KN;
    int nCnt = N - n0; if (nCnt > KN) nCnt = KN;
    if (t <= nCnt) sOff[t] = g_OFF[n0 + t];
    __syncthreads();
    int eBeg = sOff[0], eEnd = sOff[nCnt];
    if (eBeg == eEnd) return;

    for (int idx = t; idx < nCnt * 64; idx += 128) {
        int m = idx >> 6, c4 = idx & 63;
        *(float4*)(sP + m * 256 + c4 * 4) = *(const float4*)(g_P + (size_t)(n0 + m) * Dh + c4 * 4);
    }

    ull wed2[17];
#pragma unroll
    for (int j = 0; j < 17; j++) wed2[j] = *(const ull*)(g_Wed + j * 256 + 2 * t);
    ull bed2 = *(const ull*)(g_bedAll + 2 * t);

    {
        int len = eEnd - eBeg; if (len > KC) len = KC;
#pragma unroll
        for (int u = 0; u < 5; u++) {
            int idx = t + u * 128;
            if (idx < KC * 17) {
                float v = (idx < len * 17) ? g_ES[(size_t)eBeg * 17 + idx] : 0.f;
                int m = idx / 17, j = idx - m * 17;
                sES[0][m * 18 + j] = packdup(v);
            }
        }
        if (t < KC) {
            int pos = eBeg + t;
            int src = 0, nd = nCnt - 1;
            if (pos < eEnd) {
                src = g_ESRC[pos];
                nd = 0;
                for (int i = 1; i < nCnt; i++) nd += (pos >= sOff[i]);
            }
            sSrc[0][t] = src;
            sNd[0][t] = nd;
        }
    }
    __syncthreads();

    int cur = -1;
    float2 acc = make_float2(0.f, 0.f);
    ull pcur = 0ull;
    int buf = 0;

    for (int cb = eBeg; cb < eEnd; cb += KC, buf ^= 1) {
        int len = eEnd - cb; if (len > KC) len = KC;

        float nv[5];
        int nsrc = 0, nnd = nCnt - 1;
        int cb2 = cb + KC;
        bool more = (cb2 < eEnd);
        int len2 = eEnd - cb2; if (len2 > KC) len2 = KC;
#pragma unroll
        for (int u = 0; u < 5; u++) {
            int idx = t + u * 128;
            nv[u] = 0.f;
            if (more && idx < KC * 17 && idx < len2 * 17)
                nv[u] = g_ES[(size_t)cb2 * 17 + idx];
        }
        if (more && t < KC) {
            int pos = cb2 + t;
            if (pos < eEnd) {
                nsrc = g_ESRC[pos];
                nnd = 0;
                for (int i = 1; i < nCnt; i++) nnd += (pos >= sOff[i]);
            }
        }

        for (int b = 0; b < len; b += 4) {
            ull q[4];
#pragma unroll
            for (int k = 0; k < 4; k++) {
                int src = sSrc[buf][b + k];
                q[k] = *(const ull*)(g_Q + (size_t)src * Dh + 2 * t);
            }
            ull r[4] = {bed2, bed2, bed2, bed2};
            const ull* es0 = &sES[buf][b * 18];
#pragma unroll
            for (int jj = 0; jj < 8; jj++) {
                ull w0 = wed2[2 * jj], w1 = wed2[2 * jj + 1];
#pragma unroll
                for (int k = 0; k < 4; k++) {
                    ulonglong2 e2 = *(const ulonglong2*)(es0 + k * 18 + 2 * jj);
                    ffma2(r[k], e2.x, w0);
                    ffma2(r[k], e2.y, w1);
                }
            }
#pragma unroll
            for (int k = 0; k < 4; k++) ffma2(r[k], es0[k * 18 + 16], wed2[16]);
#pragma unroll
            for (int k = 0; k < 4; k++) {
                if (b + k >= len) break;
                int nd = sNd[buf][b + k];
                if (nd != cur) {
                    if (cur >= 0)
                        *(float2*)(g_R + (size_t)(n0 + cur) * Dh + 2 * t) = acc;
                    cur = nd;
                    pcur = *(const ull*)(sP + nd * 256 + 2 * t);
                    acc = make_float2(0.f, 0.f);
                }
                ull s1;
                addf2(s1, pcur, q[k]);
                addf2(s1, s1, r[k]);
                float2 f = unpk(s1);
                acc.x += fmaxf(f.x, 0.f);
                acc.y += fmaxf(f.y, 0.f);
            }
        }

        if (more) {
#pragma unroll
            for (int u = 0; u < 5; u++) {
                int idx = t + u * 128;
                if (idx < KC * 17) {
                    int m = idx / 17, j = idx - m * 17;
                    sES[buf ^ 1][m * 18 + j] = packdup(nv[u]);
                }
            }
            if (t < KC) { sSrc[buf ^ 1][t] = nsrc; sNd[buf ^ 1][t] = nnd; }
        }
        __syncthreads();
    }
    if (cur >= 0)
        *(float2*)(g_R + (size_t)(n0 + cur) * Dh + 2 * t) = acc;
}

// ---------------- k_final: R11 champion (BM=64, K=304, cp.async 2-buffer) ----------------
__global__ void __launch_bounds__(256, 2) k_final(const float* __restrict__ node_s,
                                                  const float* __restrict__ gamma, const float* __restrict__ beta,
                                                  const int* __restrict__ batch, float* __restrict__ out, int N) {
    extern __shared__ float sm[];
    float* sA = sm;                 // 64*320
    float* sB = sm + 64 * 320;      // 2 x 16*256
    float* sInv = sB + 2 * 16 * 256;
    float* sChi = sInv + 64;
    int t = threadIdx.x;
    int n0 = blockIdx.x * 64;
    const int nCh = 19;             // K = 304
    uint32_t sBa = smem_u32(sB);

    stage_B16_async(sBa, g_WBF, 0, t);
    CP_COMMIT();

    if (t < 64) {
        int n = n0 + t;
        int c = (n < N) ? g_CNT[n] : 0;
        sInv[t] = (c > 0) ? (1.f / (float)c) : 0.f;
        sChi[t] = (c > 0) ? 1.f : 0.f;
    }
    __syncthreads();
    for (int q = 0; q < 16; q++) {
        int idx = t + q * 256;
        int m = idx >> 6, c4 = idx & 63;
        int n = n0 + m;
        float4 v = make_float4(0.f, 0.f, 0.f, 0.f);
        if (n < N) {
            float inv = sInv[m];
            if (inv != 0.f) {
                float4 r = *(const float4*)(g_R + (size_t)n * Dh + c4 * 4);
                v = make_float4(r.x * inv, r.y * inv, r.z * inv, r.w * inv);
            }
        }
        *(float4*)(sA + m * 320 + c4 * 4) = v;
    }
    for (int q = 0; q < 16; q++) {
        int idx = t + q * 256;
        int m = idx >> 6, c = idx & 63;
        int n = n0 + m;
        float v = 0.f;
        if (n < N) {
            if (c < 23)      v = node_s[(size_t)n * 23 + c];
            else if (c < 39) v = g_VN[(size_t)n * 16 + (c - 23)];
        }
        sA[m * 320 + 256 + c] = v;
    }

    int i = t >> 5, j = t & 31;
    ull acc[8][4];
#pragma unroll
    for (int r = 0; r < 8; r++)
#pragma unroll
        for (int c = 0; c < 4; c++) acc[r][c] = 0ull;

    for (int ch = 0; ch < nCh; ch++) {
        if (ch + 1 < nCh) {
            stage_B16_async(sBa + (uint32_t)(((ch + 1) & 1) * 16 * Dh) * 4, g_WBF, (ch + 1) * 16, t);
            CP_COMMIT();
            CP_WAIT(1);
        } else {
            CP_WAIT(0);
        }
        __syncthreads();
        mma_chunk16(sA + i * 8 * 320 + ch * 16, 320, sB + (ch & 1) * 16 * Dh, j, acc);
        __syncthreads();
    }

    float4 b00 = *(const float4*)(g_b0 + 4 * j);
    float4 b01 = *(const float4*)(g_b0 + 128 + 4 * j);
    float4 cb0 = *(const float4*)(g_cB + 4 * j);
    float4 cb1 = *(const float4*)(g_cB + 128 + 4 * j);
    float4 g0  = *(const float4*)(gamma + 4 * j);
    float4 g1  = *(const float4*)(gamma + 128 + 4 * j);
    float4 be0 = *(const float4*)(beta + 4 * j);
    float4 be1 = *(const float4*)(beta + 128 + 4 * j);
#pragma unroll
    for (int r = 0; r < 8; r++) {
        int n = n0 + i * 8 + r;
        float chi = sChi[i * 8 + r];
        float2 a0 = unpk(acc[r][0]), a1 = unpk(acc[r][1]);
        float2 a2 = unpk(acc[r][2]), a3 = unpk(acc[r][3]);
        float f[8];
        f[0] = a0.x + b00.x + chi * cb0.x; f[1] = a0.y + b00.y + chi * cb0.y;
        f[2] = a1.x + b00.z + chi * cb0.z; f[3] = a1.y + b00.w + chi * cb0.w;
        f[4] = a2.x + b01.x + chi * cb1.x; f[5] = a2.y + b01.y + chi * cb1.y;
        f[6] = a3.x + b01.z + chi * cb1.z; f[7] = a3.y + b01.w + chi * cb1.w;
        float s = 0.f, sq = 0.f;
#pragma unroll
        for (int c = 0; c < 8; c++) { s += f[c]; sq = fmaf(f[c], f[c], sq); }
#pragma unroll
        for (int off = 16; off > 0; off >>= 1) {
            s  += __shfl_xor_sync(0xFFFFFFFFu, s, off);
            sq += __shfl_xor_sync(0xFFFFFFFFu, sq, off);
        }
        float mu = s * (1.f / 256.f);
        float var = sq * (1.f / 256.f) - mu * mu;
        float rs = rsqrtf(var + 1e-5f);
        float y[8];
        y[0] = fmaxf((f[0] - mu) * rs * g0.x + be0.x, 0.f);
        y[1] = fmaxf((f[1] - mu) * rs * g0.y + be0.y, 0.f);
        y[2] = fmaxf((f[2] - mu) * rs * g0.z + be0.z, 0.f);
        y[3] = fmaxf((f[3] - mu) * rs * g0.w + be0.w, 0.f);
        y[4] = fmaxf((f[4] - mu) * rs * g1.x + be1.x, 0.f);
        y[5] = fmaxf((f[5] - mu) * rs * g1.y + be1.y, 0.f);
        y[6] = fmaxf((f[6] - mu) * rs * g1.z + be1.z, 0.f);
        y[7] = fmaxf((f[7] - mu) * rs * g1.w + be1.w, 0.f);
        if (n < N) {
            int b = batch[n];
            atomAdd4(out + (size_t)b * Dh + 4 * j,       make_float4(y[0], y[1], y[2], y[3]));
            atomAdd4(out + (size_t)b * Dh + 128 + 4 * j, make_float4(y[4], y[5], y[6], y[7]));
        }
    }
}

// ---------------- k_div ----------------
__global__ void k_div(float* out, int G) {
    int idx = blockIdx.x * blockDim.x + threadIdx.x;
    if (idx < G * Dh) {
        float c = (float)g_GCNT[idx >> 8];
        out[idx] *= 1.f / fmaxf(c, 1.f);
    }
}

// ---------------- launch (fork/join two-stream graph) ----------------
extern "C" void kernel_launch(void* const* d_in, const int* in_sizes, int n_in,
                              void* d_out, int out_size) {
    const float* node_s     = (const float*)d_in[0];
    const float* node_v     = (const float*)d_in[1];
    const float* edge_s     = (const float*)d_in[2];
    const int*   edge_index = (const int*)d_in[3];
    const int*   batch      = (const int*)d_in[4];
    const float* Ws  = (const float*)d_in[5];
    const float* bs  = (const float*)d_in[6];
    const float* Wv  = (const float*)d_in[7];
    const float* bv  = (const float*)d_in[8];
    const float* We  = (const float*)d_in[9];
    const float* be  = (const float*)d_in[10];
    const float* Wm1 = (const float*)d_in[11];
    const float* bm1 = (const float*)d_in[12];
    const float* Wm2 = (const float*)d_in[13];
    const float* bm2 = (const float*)d_in[14];
    const float* Wn  = (const float*)d_in[15];
    const float* bn  = (const float*)d_in[16];
    const float* gamma = (const float*)d_in[17];
    const float* beta  = (const float*)d_in[18];

    int N = in_sizes[0] / 23;
    int E = in_sizes[2] / 17;
    int G = out_size / Dh;
    float* out = (float*)d_out;

    const int SM_PQ    = (64 * 64 + 2 * 16 * 256) * 4;               // 49152
    const int SM_FINAL = (64 * 320 + 2 * 16 * 256 + 128) * 4;        // 115200
    cudaFuncSetAttribute((const void*)k_pq,    cudaFuncAttributeMaxDynamicSharedMemorySize, SM_PQ);
    cudaFuncSetAttribute((const void*)k_final, cudaFuncAttributeMaxDynamicSharedMemorySize, SM_FINAL);

    // one-time resource init (first call is the uncaptured correctness run)
    static cudaStream_t s2 = nullptr;
    static cudaEvent_t evF = nullptr, evJ = nullptr;
    if (s2 == nullptr) {
        cudaStreamCreateWithFlags(&s2, cudaStreamNonBlocking);
        cudaEventCreateWithFlags(&evF, cudaEventDisableTiming);
        cudaEventCreateWithFlags(&evJ, cudaEventDisableTiming);
    }

    int mEN = (E > N) ? E : N;

    k_zero<<<456, 256>>>(out, out_size, N, G);
    cudaEventRecord(evF, 0);
    cudaStreamWaitEvent(s2, evF, 0);

    // edge pipeline (stream s2): cnt -> scan -> scatter
    k_cnt<<<(mEN + 255) / 256, 256, 0, s2>>>(edge_index, batch, E, N);
    k_scan<<<1, 1024, 0, s2>>>(N);
    k_scatter<<<(E + 255) / 256, 256, 0, s2>>>(edge_index, edge_s, E);
    cudaEventRecord(evJ, s2);

    // node pipeline (default stream): prep -> vn -> pq
    k_prep<<<468, 256>>>(Ws, bs, We, be, Wm1, bm1, Wm2, bm2, Wn, bn);
    k_vn<<<(N * 16 + 255) / 256, 256>>>(node_v, Wv, bv, N);
    dim3 gpq((N + 63) / 64, 2);
    k_pq<<<gpq, 256, SM_PQ>>>(node_s, N);

    cudaStreamWaitEvent(0, evJ, 0);
    k_msgs<<<(N + KN - 1) / KN, 128>>>(N);
    k_final<<<(N + 63) / 64, 256, SM_FINAL>>>(node_s, gamma, beta, batch, out, N);
    k_div<<<(G * Dh + 255) / 256, 256>>>(out, G);
}